// round 7
// baseline (speedup 1.0000x reference)
#include <cuda_runtime.h>
#include <cuda_fp16.h>
#include <cstdint>
#include <cstddef>

typedef unsigned int u32;

#define Bq 4
#define Sq 2048
#define Dm 1024
#define Hh 16
#define DP 64
#define MTOK (Bq*Sq)          /* 8192 */
#define NBH  (Bq*Hh)          /* 64   */
#define OUT_ELEMS (MTOK*Dm)   /* 8388608 */

// Scratch (allocation-free rule: __device__ globals)
__device__ float g_q[(size_t)NBH*Sq*DP];
__device__ float g_k[(size_t)NBH*Sq*DP];
__device__ float g_v[(size_t)NBH*Sq*DP];
__device__ float g_rep[(size_t)MTOK*Dm];
__device__ float g_rowsum[(size_t)NBH*Sq];
__device__ float g_attn_fallback[(size_t)NBH*Sq*Sq];

// ---------------------------------------------------------------------------
// helpers
// ---------------------------------------------------------------------------
__device__ __forceinline__ u32 saddr(const void* p) {
    return (u32)__cvta_generic_to_shared(p);
}
__device__ __forceinline__ u32 hpair(float a, float b) {
    __half2 t = __floats2half2_rn(a, b);
    return *reinterpret_cast<u32*>(&t);
}

__device__ __forceinline__ void mma16816(float* c, const u32* a, const u32* b) {
    asm volatile(
        "mma.sync.aligned.m16n8k16.row.col.f32.f16.f16.f32 "
        "{%0,%1,%2,%3},{%4,%5,%6,%7},{%8,%9},{%0,%1,%2,%3};"
        : "+f"(c[0]), "+f"(c[1]), "+f"(c[2]), "+f"(c[3])
        : "r"(a[0]), "r"(a[1]), "r"(a[2]), "r"(a[3]), "r"(b[0]), "r"(b[1]));
}
__device__ __forceinline__ void ldsm4(u32* r, u32 a) {
    asm volatile("ldmatrix.sync.aligned.m8n8.x4.shared.b16 {%0,%1,%2,%3},[%4];"
                 : "=r"(r[0]), "=r"(r[1]), "=r"(r[2]), "=r"(r[3]) : "r"(a));
}
__device__ __forceinline__ void ldsm4t(u32* r, u32 a) {
    asm volatile("ldmatrix.sync.aligned.m8n8.x4.trans.shared.b16 {%0,%1,%2,%3},[%4];"
                 : "=r"(r[0]), "=r"(r[1]), "=r"(r[2]), "=r"(r[3]) : "r"(a));
}

#define PAW 36   /* 64-fp16 row: 32 words + 4 pad (144B pitch, conflict-free) */
#define PBW 68   /* 128-fp16 row: 64 words + 4 pad (272B pitch) */

__global__ void zero_rowsum_kernel() {
    int i = blockIdx.x * 256 + threadIdx.x;
    g_rowsum[i] = 0.0f;
}

// ---------------------------------------------------------------------------
// Projection GEMM (plain fp16): Y = X @ W + b, M=8192 N=1024 K=1024.
// Block 128x128, 8 warps (2x4), warp tile 64x32, K-tile 64.
// target 0/1/2 -> head-split to g_q/g_k/g_v ; 3 -> row-major to dout.
// ---------------------------------------------------------------------------
__global__ __launch_bounds__(256) void proj_mma(
    const float* __restrict__ X, const float* __restrict__ W,
    const float* __restrict__ bias, float* __restrict__ dout, int target)
{
    __shared__ __align__(16) u32 As[128 * PAW];   // [m][k/2 words]
    __shared__ __align__(16) u32 Bs[64 * PBW];    // [k][n/2 words]
    if (X == nullptr) X = g_rep;

    const int tid = threadIdx.x;
    const int m0 = blockIdx.x * 128, n0 = blockIdx.y * 128;
    const int warp = tid >> 5, lane = tid & 31;
    const int wm = (warp >> 2) * 64, wn = (warp & 3) * 32;
    const int g = lane >> 2, tig = lane & 3;

    const int a_row = (lane & 7) + ((lane >> 3) & 1) * 8;
    const int a_k   = (lane >> 4) * 8;
    const int bt_k  = (lane & 7) + ((lane >> 3) & 1) * 8;
    const int bt_n  = (lane >> 4) * 8;

    const u32 as_base = saddr(As), bs_base = saddr(Bs);

    float acc[4][4][4];
#pragma unroll
    for (int i = 0; i < 4; i++) {
#pragma unroll
        for (int j = 0; j < 4; j++) {
#pragma unroll
            for (int r = 0; r < 4; r++) { acc[i][j][r] = 0.0f; }
        }
    }

    for (int k0 = 0; k0 < Dm; k0 += 64) {
#pragma unroll
        for (int l = 0; l < 8; l++) {
            int idx = tid + l * 256;
            int r = idx >> 4, q = idx & 15;           // 16 float4 per 64-float row
            float4 v = *(const float4*)&X[(size_t)(m0 + r) * Dm + k0 + q * 4];
            uint2 w;
            w.x = hpair(v.x, v.y); w.y = hpair(v.z, v.w);
            *(uint2*)&As[r * PAW + q * 2] = w;
        }
#pragma unroll
        for (int l = 0; l < 8; l++) {
            int idx = tid + l * 256;
            int r = idx >> 5, q = idx & 31;           // 32 float4 per 128-float k-row
            float4 v = *(const float4*)&W[(size_t)(k0 + r) * Dm + n0 + q * 4];
            uint2 w;
            w.x = hpair(v.x, v.y); w.y = hpair(v.z, v.w);
            *(uint2*)&Bs[r * PBW + q * 2] = w;
        }
        __syncthreads();
#pragma unroll
        for (int ks = 0; ks < 64; ks += 16) {
            u32 af[4][4];
#pragma unroll
            for (int mi = 0; mi < 4; mi++) {
                ldsm4(af[mi], as_base + (u32)((wm + mi * 16 + a_row) * PAW + ((ks + a_k) >> 1)) * 4u);
            }
            u32 bf[2][4];
#pragma unroll
            for (int h = 0; h < 2; h++) {
                ldsm4t(bf[h], bs_base + (u32)((ks + bt_k) * PBW + ((wn + h * 16 + bt_n) >> 1)) * 4u);
            }
#pragma unroll
            for (int mi = 0; mi < 4; mi++) {
#pragma unroll
                for (int j = 0; j < 4; j++) {
                    mma16816(acc[mi][j], af[mi], &bf[j >> 1][(j & 1) * 2]);
                }
            }
        }
        __syncthreads();
    }

    float* hs_out = (target == 0) ? g_q : (target == 1) ? g_k : g_v;
#pragma unroll
    for (int mi = 0; mi < 4; mi++) {
        int row = m0 + wm + mi * 16 + g;
        int row2 = row + 8;
#pragma unroll
        for (int j = 0; j < 4; j++) {
            int col = n0 + wn + j * 8 + tig * 2;
            float b0 = bias[col], b1 = bias[col + 1];
            float2 v0 = make_float2(acc[mi][j][0] + b0, acc[mi][j][1] + b1);
            float2 v1 = make_float2(acc[mi][j][2] + b0, acc[mi][j][3] + b1);
            if (target < 3) {
                int h = col >> 6, dc = col & 63;
                int bi = row >> 11, sl = row & 2047;
                int bi2 = row2 >> 11, sl2 = row2 & 2047;
                *(float2*)&hs_out[((size_t)(bi * Hh + h) * Sq + sl) * DP + dc] = v0;
                *(float2*)&hs_out[((size_t)(bi2 * Hh + h) * Sq + sl2) * DP + dc] = v1;
            } else {
                *(float2*)&dout[(size_t)row * Dm + col] = v0;
                *(float2*)&dout[(size_t)row2 * Dm + col] = v1;
            }
        }
    }
}

// ---------------------------------------------------------------------------
// Scores (plain fp16): e = mask ? 0 : exp(0.125 * q.k). Unnormalized + rowsums.
// Per (b,h): M=N=2048 K=64 (single K-tile, no loop). Block 128x128, warps 2x4.
// ---------------------------------------------------------------------------
__global__ __launch_bounds__(256) void scores_mma(
    const float* __restrict__ Mask, float* __restrict__ attn)
{
    __shared__ __align__(16) u32 As[128 * PAW];
    __shared__ __align__(16) u32 Bs[128 * PAW];
    const int tid = threadIdx.x;
    const int bh = blockIdx.z, b = bh >> 4;
    const int m0 = blockIdx.x * 128, n0 = blockIdx.y * 128;
    const float* Qp = g_q + (size_t)bh * Sq * DP;
    const float* Kp = g_k + (size_t)bh * Sq * DP;
    const int warp = tid >> 5, lane = tid & 31;
    const int wm = (warp >> 2) * 64, wn = (warp & 3) * 32;
    const int g = lane >> 2, tig = lane & 3;

    const int a_row = (lane & 7) + ((lane >> 3) & 1) * 8;
    const int a_k   = (lane >> 4) * 8;
    const int bn_n  = (lane & 7) + (lane >> 4) * 8;     // no-trans B: n row
    const int bn_k  = ((lane >> 3) & 1) * 8;            // no-trans B: k offset

    const u32 as_base = saddr(As), bs_base = saddr(Bs);

    float acc[4][4][4];
#pragma unroll
    for (int i = 0; i < 4; i++) {
#pragma unroll
        for (int j = 0; j < 4; j++) {
#pragma unroll
            for (int r = 0; r < 4; r++) { acc[i][j][r] = 0.0f; }
        }
    }

    // single K-tile: whole DP=64 loaded at once
#pragma unroll
    for (int l = 0; l < 8; l++) {
        int idx = tid + l * 256;
        int r = idx >> 4, q = idx & 15;
        float4 v = *(const float4*)&Qp[(size_t)(m0 + r) * DP + q * 4];
        uint2 w;
        w.x = hpair(v.x, v.y); w.y = hpair(v.z, v.w);
        *(uint2*)&As[r * PAW + q * 2] = w;
        float4 v2 = *(const float4*)&Kp[(size_t)(n0 + r) * DP + q * 4];
        uint2 w2;
        w2.x = hpair(v2.x, v2.y); w2.y = hpair(v2.z, v2.w);
        *(uint2*)&Bs[r * PAW + q * 2] = w2;
    }
    __syncthreads();
#pragma unroll
    for (int ks = 0; ks < 64; ks += 16) {
        u32 af[4][4];
#pragma unroll
        for (int mi = 0; mi < 4; mi++) {
            ldsm4(af[mi], as_base + (u32)((wm + mi * 16 + a_row) * PAW + ((ks + a_k) >> 1)) * 4u);
        }
        u32 bf[2][4];
#pragma unroll
        for (int h = 0; h < 2; h++) {
            ldsm4(bf[h], bs_base + (u32)((wn + h * 16 + bn_n) * PAW + ((ks + bn_k) >> 1)) * 4u);
        }
#pragma unroll
        for (int mi = 0; mi < 4; mi++) {
#pragma unroll
            for (int j = 0; j < 4; j++) {
                mma16816(acc[mi][j], af[mi], &bf[j >> 1][(j & 1) * 2]);
            }
        }
    }

    const float scale = 0.125f;
#pragma unroll
    for (int mi = 0; mi < 4; mi++) {
        int r0 = m0 + wm + mi * 16 + g;
        int r1 = r0 + 8;
        const float* mr0 = Mask + ((size_t)b * Sq + r0) * Sq;
        const float* mr1 = Mask + ((size_t)b * Sq + r1) * Sq;
        float* ar0 = attn + ((size_t)bh * Sq + r0) * Sq;
        float* ar1 = attn + ((size_t)bh * Sq + r1) * Sq;
        float rs0 = 0.0f, rs1 = 0.0f;
#pragma unroll
        for (int j = 0; j < 4; j++) {
            int col = n0 + wn + j * 8 + tig * 2;
            float2 mv0 = *(const float2*)&mr0[col];
            float2 mv1 = *(const float2*)&mr1[col];
            float e00 = (mv0.x != 0.0f) ? 0.0f : __expf(acc[mi][j][0] * scale);
            float e01 = (mv0.y != 0.0f) ? 0.0f : __expf(acc[mi][j][1] * scale);
            float e10 = (mv1.x != 0.0f) ? 0.0f : __expf(acc[mi][j][2] * scale);
            float e11 = (mv1.y != 0.0f) ? 0.0f : __expf(acc[mi][j][3] * scale);
            *(float2*)&ar0[col] = make_float2(e00, e01);
            *(float2*)&ar1[col] = make_float2(e10, e11);
            rs0 += e00 + e01;
            rs1 += e10 + e11;
        }
        rs0 += __shfl_xor_sync(0xffffffffu, rs0, 1);
        rs0 += __shfl_xor_sync(0xffffffffu, rs0, 2);
        rs1 += __shfl_xor_sync(0xffffffffu, rs1, 1);
        rs1 += __shfl_xor_sync(0xffffffffu, rs1, 2);
        if (tig == 0) {
            atomicAdd(&g_rowsum[(size_t)bh * Sq + r0], rs0);
            atomicAdd(&g_rowsum[(size_t)bh * Sq + r1], rs1);
        }
    }
}

// ---------------------------------------------------------------------------
// AV (plain fp16): rep = softmax(attn) @ v. Normalizes attn IN PLACE during
// its only read. Per (b,h): M=2048 N=64 K=2048. Block 128x64, warps 4x2,
// K-tile 64.
// ---------------------------------------------------------------------------
__global__ __launch_bounds__(256) void av_mma(float* __restrict__ attn)
{
    __shared__ __align__(16) u32 As[128 * PAW];
    __shared__ __align__(16) u32 Bs[64 * PAW];
    __shared__ float inv_s[128];
    const int tid = threadIdx.x;
    const int bh = blockIdx.y, b = bh >> 4, h = bh & 15;
    const int m0 = blockIdx.x * 128;
    const float* Vp = g_v + (size_t)bh * Sq * DP;
    float* Ap = attn + (size_t)bh * Sq * Sq;
    const int warp = tid >> 5, lane = tid & 31;
    const int wm = (warp >> 1) * 32, wn = (warp & 1) * 32;
    const int g = lane >> 2, tig = lane & 3;

    const int a_row = (lane & 7) + ((lane >> 3) & 1) * 8;
    const int a_k   = (lane >> 4) * 8;
    const int bt_k  = (lane & 7) + ((lane >> 3) & 1) * 8;
    const int bt_n  = (lane >> 4) * 8;

    const u32 as_base = saddr(As), bs_base = saddr(Bs);

    if (tid < 128) { inv_s[tid] = 1.0f / g_rowsum[(size_t)bh * Sq + m0 + tid]; }
    __syncthreads();

    float acc[2][4][4];
#pragma unroll
    for (int i = 0; i < 2; i++) {
#pragma unroll
        for (int j = 0; j < 4; j++) {
#pragma unroll
            for (int r = 0; r < 4; r++) { acc[i][j][r] = 0.0f; }
        }
    }

    for (int k0 = 0; k0 < Sq; k0 += 64) {
#pragma unroll
        for (int l = 0; l < 8; l++) {
            int idx = tid + l * 256;
            int r = idx >> 4, q = idx & 15;
            float* p = &Ap[(size_t)(m0 + r) * Sq + k0 + q * 4];
            float4 v = *(const float4*)p;
            float iv = inv_s[r];
            *(float4*)p = make_float4(v.x * iv, v.y * iv, v.z * iv, v.w * iv);
            uint2 w;
            w.x = hpair(v.x, v.y); w.y = hpair(v.z, v.w);
            *(uint2*)&As[r * PAW + q * 2] = w;
        }
#pragma unroll
        for (int l = 0; l < 4; l++) {
            int idx = tid + l * 256;
            int r = idx >> 4, q = idx & 15;          // 16 float4 per 64-float V row
            float4 v = *(const float4*)&Vp[(size_t)(k0 + r) * DP + q * 4];
            uint2 w;
            w.x = hpair(v.x, v.y); w.y = hpair(v.z, v.w);
            *(uint2*)&Bs[r * PAW + q * 2] = w;
        }
        __syncthreads();
#pragma unroll
        for (int ks = 0; ks < 64; ks += 16) {
            u32 af[2][4];
#pragma unroll
            for (int mi = 0; mi < 2; mi++) {
                ldsm4(af[mi], as_base + (u32)((wm + mi * 16 + a_row) * PAW + ((ks + a_k) >> 1)) * 4u);
            }
            u32 bf[2][4];
#pragma unroll
            for (int hh = 0; hh < 2; hh++) {
                ldsm4t(bf[hh], bs_base + (u32)((ks + bt_k) * PAW + ((wn + hh * 16 + bt_n) >> 1)) * 4u);
            }
#pragma unroll
            for (int mi = 0; mi < 2; mi++) {
#pragma unroll
                for (int j = 0; j < 4; j++) {
                    mma16816(acc[mi][j], af[mi], &bf[j >> 1][(j & 1) * 2]);
                }
            }
        }
        __syncthreads();
    }

#pragma unroll
    for (int mi = 0; mi < 2; mi++) {
        int row = m0 + wm + mi * 16 + g;
        int row2 = row + 8;
        float iv0 = inv_s[row - m0], iv1 = inv_s[row2 - m0];
#pragma unroll
        for (int j = 0; j < 4; j++) {
            int col = wn + j * 8 + tig * 2;
            float2 v0 = make_float2(acc[mi][j][0] * iv0, acc[mi][j][1] * iv0);
            float2 v1 = make_float2(acc[mi][j][2] * iv1, acc[mi][j][3] * iv1);
            *(float2*)&g_rep[(size_t)(b * Sq + row) * Dm + h * DP + col] = v0;
            *(float2*)&g_rep[(size_t)(b * Sq + row2) * Dm + h * DP + col] = v1;
        }
    }
}

// ---------------------------------------------------------------------------
extern "C" void kernel_launch(void* const* d_in, const int* in_sizes, int n_in,
                              void* d_out, int out_size)
{
    const float* Q    = (const float*)d_in[0];
    const float* K    = (const float*)d_in[1];
    const float* V    = (const float*)d_in[2];
    const float* Mask = (const float*)d_in[3];
    const float* Wq   = (const float*)d_in[4];
    const float* bq   = (const float*)d_in[5];
    const float* Wk   = (const float*)d_in[6];
    const float* bk   = (const float*)d_in[7];
    const float* Wv   = (const float*)d_in[8];
    const float* bv   = (const float*)d_in[9];
    const float* Wo   = (const float*)d_in[10];
    const float* bo   = (const float*)d_in[11];

    float* out = (float*)d_out;

    float* attn;
    const size_t attn_elems = (size_t)NBH * Sq * Sq;
    if ((size_t)out_size >= (size_t)OUT_ELEMS + attn_elems) {
        attn = out + OUT_ELEMS;
    } else {
        void* p = nullptr;
        cudaGetSymbolAddress(&p, g_attn_fallback);
        attn = (float*)p;
    }

    zero_rowsum_kernel<<<(NBH * Sq) / 256, 256>>>();

    dim3 gProj(MTOK / 128, Dm / 128);            // 64 x 8
    proj_mma<<<gProj, 256>>>(Q, Wq, bq, nullptr, 0);
    proj_mma<<<gProj, 256>>>(K, Wk, bk, nullptr, 1);
    proj_mma<<<gProj, 256>>>(V, Wv, bv, nullptr, 2);

    dim3 gScore(Sq / 128, Sq / 128, NBH);        // 16 x 16 x 64
    scores_mma<<<gScore, 256>>>(Mask, attn);

    dim3 gAV(Sq / 128, NBH);                     // 16 x 64
    av_mma<<<gAV, 256>>>(attn);

    proj_mma<<<gProj, 256>>>(nullptr, Wo, bo, out, 3);
}

// round 8
// speedup vs baseline: 1.1486x; 1.1486x over previous
#include <cuda_runtime.h>
#include <cuda_fp16.h>
#include <cstdint>
#include <cstddef>

typedef unsigned int u32;

#define Bq 4
#define Sq 2048
#define Dm 1024
#define Hh 16
#define DP 64
#define MTOK (Bq*Sq)          /* 8192 */
#define NBH  (Bq*Hh)          /* 64   */
#define OUT_ELEMS (MTOK*Dm)   /* 8388608 */
#define NMW (Sq/32)           /* 64 mask words per row */

// Scratch (allocation-free rule: __device__ globals)
__device__ __half g_q16[(size_t)NBH*Sq*DP];
__device__ __half g_k16[(size_t)NBH*Sq*DP];
__device__ __half g_v16[(size_t)NBH*Sq*DP];
__device__ __half g_rep16[(size_t)MTOK*Dm];
__device__ float  g_rowsum[(size_t)NBH*Sq];
__device__ u32    g_mbits[(size_t)Bq*Sq*NMW];
__device__ float  g_attn_fallback[(size_t)NBH*Sq*Sq];

// ---------------------------------------------------------------------------
// helpers
// ---------------------------------------------------------------------------
__device__ __forceinline__ u32 saddr(const void* p) {
    return (u32)__cvta_generic_to_shared(p);
}
__device__ __forceinline__ u32 hpair(float a, float b) {
    __half2 t = __floats2half2_rn(a, b);
    return *reinterpret_cast<u32*>(&t);
}
__device__ __forceinline__ void mma16816(float* c, const u32* a, const u32* b) {
    asm volatile(
        "mma.sync.aligned.m16n8k16.row.col.f32.f16.f16.f32 "
        "{%0,%1,%2,%3},{%4,%5,%6,%7},{%8,%9},{%0,%1,%2,%3};"
        : "+f"(c[0]), "+f"(c[1]), "+f"(c[2]), "+f"(c[3])
        : "r"(a[0]), "r"(a[1]), "r"(a[2]), "r"(a[3]), "r"(b[0]), "r"(b[1]));
}
__device__ __forceinline__ void ldsm4(u32* r, u32 a) {
    asm volatile("ldmatrix.sync.aligned.m8n8.x4.shared.b16 {%0,%1,%2,%3},[%4];"
                 : "=r"(r[0]), "=r"(r[1]), "=r"(r[2]), "=r"(r[3]) : "r"(a));
}
__device__ __forceinline__ void ldsm4t(u32* r, u32 a) {
    asm volatile("ldmatrix.sync.aligned.m8n8.x4.trans.shared.b16 {%0,%1,%2,%3},[%4];"
                 : "=r"(r[0]), "=r"(r[1]), "=r"(r[2]), "=r"(r[3]) : "r"(a));
}

#define PAW 36   /* 64-fp16 row: 32 words + 4 pad (144B pitch) */
#define PBW 68   /* 128-fp16 row: 64 words + 4 pad (272B pitch) */

// ---------------------------------------------------------------------------
// Mask -> bitmask. 1 bit per mask element (1 = masked). Warp ballot pack.
// ---------------------------------------------------------------------------
__global__ __launch_bounds__(256) void mask_bits_kernel(const float* __restrict__ M)
{
    int wgl = blockIdx.x * 8 + (threadIdx.x >> 5);   // global warp id
    int lane = threadIdx.x & 31;
#pragma unroll
    for (int i = 0; i < 8; i++) {
        size_t word = (size_t)wgl * 8 + i;
        float v = M[word * 32 + lane];
        u32 bal = __ballot_sync(0xffffffffu, v != 0.0f);
        if (lane == 0) { g_mbits[word] = bal; }
    }
}

// ---------------------------------------------------------------------------
// Projection GEMM: Y = X @ W + b, M=8192 N=1024 K=1024, fp16 MMA.
// targets 0/1/2: fp32 X input -> fp16 head-split out (g_q16/g_k16/g_v16).
// target 3: fp16 X = g_rep16 -> fp32 row-major dout.
// ---------------------------------------------------------------------------
__global__ __launch_bounds__(256) void proj_mma(
    const float* __restrict__ X, const float* __restrict__ W,
    const float* __restrict__ bias, float* __restrict__ dout, int target)
{
    __shared__ __align__(16) u32 As[128 * PAW];   // [m][k/2 words]
    __shared__ __align__(16) u32 Bs[64 * PBW];    // [k][n/2 words]

    const int tid = threadIdx.x;
    const int m0 = blockIdx.x * 128, n0 = blockIdx.y * 128;
    const int warp = tid >> 5, lane = tid & 31;
    const int wm = (warp >> 2) * 64, wn = (warp & 3) * 32;
    const int g = lane >> 2, tig = lane & 3;

    const int a_row = (lane & 7) + ((lane >> 3) & 1) * 8;
    const int a_k   = (lane >> 4) * 8;
    const int bt_k  = (lane & 7) + ((lane >> 3) & 1) * 8;
    const int bt_n  = (lane >> 4) * 8;

    const u32 as_base = saddr(As), bs_base = saddr(Bs);

    float acc[4][4][4];
#pragma unroll
    for (int i = 0; i < 4; i++) {
#pragma unroll
        for (int j = 0; j < 4; j++) {
#pragma unroll
            for (int r = 0; r < 4; r++) { acc[i][j][r] = 0.0f; }
        }
    }

    for (int k0 = 0; k0 < Dm; k0 += 64) {
        if (target < 3) {
#pragma unroll
            for (int l = 0; l < 8; l++) {
                int idx = tid + l * 256;
                int r = idx >> 4, q = idx & 15;
                float4 v = *(const float4*)&X[(size_t)(m0 + r) * Dm + k0 + q * 4];
                uint2 w;
                w.x = hpair(v.x, v.y); w.y = hpair(v.z, v.w);
                *(uint2*)&As[r * PAW + q * 2] = w;
            }
        } else {
            const __half* X16 = g_rep16;
#pragma unroll
            for (int l = 0; l < 4; l++) {
                int idx = tid + l * 256;
                int r = idx >> 3, q = idx & 7;
                *(uint4*)&As[r * PAW + q * 4] =
                    *(const uint4*)&X16[(size_t)(m0 + r) * Dm + k0 + q * 8];
            }
        }
#pragma unroll
        for (int l = 0; l < 8; l++) {
            int idx = tid + l * 256;
            int r = idx >> 5, q = idx & 31;
            float4 v = *(const float4*)&W[(size_t)(k0 + r) * Dm + n0 + q * 4];
            uint2 w;
            w.x = hpair(v.x, v.y); w.y = hpair(v.z, v.w);
            *(uint2*)&Bs[r * PBW + q * 2] = w;
        }
        __syncthreads();
#pragma unroll
        for (int ks = 0; ks < 64; ks += 16) {
            u32 af[4][4];
#pragma unroll
            for (int mi = 0; mi < 4; mi++) {
                ldsm4(af[mi], as_base + (u32)((wm + mi * 16 + a_row) * PAW + ((ks + a_k) >> 1)) * 4u);
            }
            u32 bf[2][4];
#pragma unroll
            for (int h = 0; h < 2; h++) {
                ldsm4t(bf[h], bs_base + (u32)((ks + bt_k) * PBW + ((wn + h * 16 + bt_n) >> 1)) * 4u);
            }
#pragma unroll
            for (int mi = 0; mi < 4; mi++) {
#pragma unroll
                for (int j = 0; j < 4; j++) {
                    mma16816(acc[mi][j], af[mi], &bf[j >> 1][(j & 1) * 2]);
                }
            }
        }
        __syncthreads();
    }

    __half* hs_out = (target == 0) ? g_q16 : (target == 1) ? g_k16 : g_v16;
#pragma unroll
    for (int mi = 0; mi < 4; mi++) {
        int row = m0 + wm + mi * 16 + g;
        int row2 = row + 8;
#pragma unroll
        for (int j = 0; j < 4; j++) {
            int col = n0 + wn + j * 8 + tig * 2;
            float b0 = bias[col], b1 = bias[col + 1];
            float c00 = acc[mi][j][0] + b0, c01 = acc[mi][j][1] + b1;
            float c10 = acc[mi][j][2] + b0, c11 = acc[mi][j][3] + b1;
            if (target < 3) {
                int h = col >> 6, dc = col & 63;
                int bi = row >> 11, sl = row & 2047;
                int bi2 = row2 >> 11, sl2 = row2 & 2047;
                *(u32*)&hs_out[((size_t)(bi * Hh + h) * Sq + sl) * DP + dc] = hpair(c00, c01);
                *(u32*)&hs_out[((size_t)(bi2 * Hh + h) * Sq + sl2) * DP + dc] = hpair(c10, c11);
            } else {
                *(float2*)&dout[(size_t)row * Dm + col] = make_float2(c00, c01);
                *(float2*)&dout[(size_t)row2 * Dm + col] = make_float2(c10, c11);
            }
        }
    }
}

// ---------------------------------------------------------------------------
// S1: row sums of unnormalized masked exp. Block owns 128 full rows of one bh.
// grid (16, 64), 8 warps, warp = 16 rows. No atomics, no attn store.
// ---------------------------------------------------------------------------
__global__ __launch_bounds__(256) void rowsum_mma()
{
    __shared__ __align__(16) u32 Qs[128 * PAW];
    __shared__ __align__(16) u32 Ks[128 * PAW];
    __shared__ __align__(16) uint4 Ms[128];
    const int tid = threadIdx.x;
    const int bh = blockIdx.y, b = bh >> 4;
    const int m0 = blockIdx.x * 128;
    const __half* Qp = g_q16 + (size_t)bh * Sq * DP;
    const __half* Kp = g_k16 + (size_t)bh * Sq * DP;
    const int warp = tid >> 5, lane = tid & 31;
    const int wm = warp * 16;
    const int g = lane >> 2, tig = lane & 3;

    const int a_row = (lane & 7) + ((lane >> 3) & 1) * 8;
    const int a_k   = (lane >> 4) * 8;
    const int bn_n  = (lane & 7) + (lane >> 4) * 8;
    const int bn_k  = ((lane >> 3) & 1) * 8;

    const u32 qs_base = saddr(Qs), ks_base = saddr(Ks);

#pragma unroll
    for (int l = 0; l < 4; l++) {
        int idx = tid + l * 256;
        int r = idx >> 3, q = idx & 7;
        *(uint4*)&Qs[r * PAW + q * 4] = *(const uint4*)&Qp[(size_t)(m0 + r) * DP + q * 8];
    }
    __syncthreads();

    u32 af[4][4];
#pragma unroll
    for (int ks = 0; ks < 4; ks++) {
        ldsm4(af[ks], qs_base + (u32)((wm + a_row) * PAW + ((ks * 16 + a_k) >> 1)) * 4u);
    }

    const float scale = 0.125f;
    float rs0 = 0.0f, rs1 = 0.0f;

    for (int n0 = 0; n0 < Sq; n0 += 128) {
        __syncthreads();
#pragma unroll
        for (int l = 0; l < 4; l++) {
            int idx = tid + l * 256;
            int r = idx >> 3, q = idx & 7;
            *(uint4*)&Ks[r * PAW + q * 4] = *(const uint4*)&Kp[(size_t)(n0 + r) * DP + q * 8];
        }
        if (tid < 128) {
            Ms[tid] = *(const uint4*)&g_mbits[(size_t)(b * Sq + m0 + tid) * NMW + (n0 >> 5)];
        }
        __syncthreads();

        float sc[16][4];
#pragma unroll
        for (int t = 0; t < 16; t++) {
#pragma unroll
            for (int r = 0; r < 4; r++) { sc[t][r] = 0.0f; }
        }
#pragma unroll
        for (int ks = 0; ks < 4; ks++) {
#pragma unroll
            for (int h6 = 0; h6 < 8; h6++) {
                u32 bq[4];
                ldsm4(bq, ks_base + (u32)((h6 * 16 + bn_n) * PAW + ((ks * 16 + bn_k) >> 1)) * 4u);
                mma16816(sc[2 * h6], af[ks], &bq[0]);
                mma16816(sc[2 * h6 + 1], af[ks], &bq[2]);
            }
        }

        uint4 mq0 = Ms[wm + g];
        uint4 mq1 = Ms[wm + g + 8];
        const u32* mw0 = (const u32*)&mq0;
        const u32* mw1 = (const u32*)&mq1;
#pragma unroll
        for (int t = 0; t < 16; t++) {
            int bp = t * 8 + tig * 2;
            u32 b0 = (mw0[bp >> 5] >> (bp & 31)) & 3u;
            u32 b1 = (mw1[bp >> 5] >> (bp & 31)) & 3u;
            rs0 += ((b0 & 1u) ? 0.0f : __expf(sc[t][0] * scale))
                 + ((b0 & 2u) ? 0.0f : __expf(sc[t][1] * scale));
            rs1 += ((b1 & 1u) ? 0.0f : __expf(sc[t][2] * scale))
                 + ((b1 & 2u) ? 0.0f : __expf(sc[t][3] * scale));
        }
    }

    rs0 += __shfl_xor_sync(0xffffffffu, rs0, 1);
    rs0 += __shfl_xor_sync(0xffffffffu, rs0, 2);
    rs1 += __shfl_xor_sync(0xffffffffu, rs1, 1);
    rs1 += __shfl_xor_sync(0xffffffffu, rs1, 2);
    if (tig == 0) {
        g_rowsum[(size_t)bh * Sq + m0 + wm + g] = rs0;
        g_rowsum[(size_t)bh * Sq + m0 + wm + g + 8] = rs1;
    }
}

// ---------------------------------------------------------------------------
// S2: recompute QK, normalize with S1 sums, store normalized attn (once),
// and accumulate O = P @ V via in-register P repack. grid (16, 64), 8 warps.
// ---------------------------------------------------------------------------
__global__ __launch_bounds__(256) void attn_av_mma(float* __restrict__ attn)
{
    __shared__ __align__(16) u32 Qs[128 * PAW];
    __shared__ __align__(16) u32 Ks[128 * PAW];
    __shared__ __align__(16) u32 Vs[128 * PAW];
    __shared__ __align__(16) uint4 Ms[128];
    __shared__ float inv_s[128];
    const int tid = threadIdx.x;
    const int bh = blockIdx.y, b = bh >> 4, h = bh & 15;
    const int m0 = blockIdx.x * 128;
    const __half* Qp = g_q16 + (size_t)bh * Sq * DP;
    const __half* Kp = g_k16 + (size_t)bh * Sq * DP;
    const __half* Vp = g_v16 + (size_t)bh * Sq * DP;
    const int warp = tid >> 5, lane = tid & 31;
    const int wm = warp * 16;
    const int g = lane >> 2, tig = lane & 3;

    const int a_row = (lane & 7) + ((lane >> 3) & 1) * 8;
    const int a_k   = (lane >> 4) * 8;
    const int bn_n  = (lane & 7) + (lane >> 4) * 8;
    const int bn_k  = ((lane >> 3) & 1) * 8;
    const int bt_k  = (lane & 7) + ((lane >> 3) & 1) * 8;
    const int bt_n  = (lane >> 4) * 8;

    const u32 qs_base = saddr(Qs), ks_base = saddr(Ks), vs_base = saddr(Vs);

#pragma unroll
    for (int l = 0; l < 4; l++) {
        int idx = tid + l * 256;
        int r = idx >> 3, q = idx & 7;
        *(uint4*)&Qs[r * PAW + q * 4] = *(const uint4*)&Qp[(size_t)(m0 + r) * DP + q * 8];
    }
    if (tid < 128) { inv_s[tid] = 1.0f / g_rowsum[(size_t)bh * Sq + m0 + tid]; }
    __syncthreads();

    u32 af[4][4];
#pragma unroll
    for (int ks = 0; ks < 4; ks++) {
        ldsm4(af[ks], qs_base + (u32)((wm + a_row) * PAW + ((ks * 16 + a_k) >> 1)) * 4u);
    }
    const float iv0 = inv_s[wm + g];
    const float iv1 = inv_s[wm + g + 8];

    float o[8][4];
#pragma unroll
    for (int t = 0; t < 8; t++) {
#pragma unroll
        for (int r = 0; r < 4; r++) { o[t][r] = 0.0f; }
    }

    const float scale = 0.125f;
    float* ar0 = attn + ((size_t)bh * Sq + m0 + wm + g) * Sq;
    float* ar1 = attn + ((size_t)bh * Sq + m0 + wm + g + 8) * Sq;

    for (int n0 = 0; n0 < Sq; n0 += 128) {
        __syncthreads();
#pragma unroll
        for (int l = 0; l < 4; l++) {
            int idx = tid + l * 256;
            int r = idx >> 3, q = idx & 7;
            *(uint4*)&Ks[r * PAW + q * 4] = *(const uint4*)&Kp[(size_t)(n0 + r) * DP + q * 8];
            *(uint4*)&Vs[r * PAW + q * 4] = *(const uint4*)&Vp[(size_t)(n0 + r) * DP + q * 8];
        }
        if (tid < 128) {
            Ms[tid] = *(const uint4*)&g_mbits[(size_t)(b * Sq + m0 + tid) * NMW + (n0 >> 5)];
        }
        __syncthreads();

        float sc[16][4];
#pragma unroll
        for (int t = 0; t < 16; t++) {
#pragma unroll
            for (int r = 0; r < 4; r++) { sc[t][r] = 0.0f; }
        }
#pragma unroll
        for (int ks = 0; ks < 4; ks++) {
#pragma unroll
            for (int h6 = 0; h6 < 8; h6++) {
                u32 bq[4];
                ldsm4(bq, ks_base + (u32)((h6 * 16 + bn_n) * PAW + ((ks * 16 + bn_k) >> 1)) * 4u);
                mma16816(sc[2 * h6], af[ks], &bq[0]);
                mma16816(sc[2 * h6 + 1], af[ks], &bq[2]);
            }
        }

        uint4 mq0 = Ms[wm + g];
        uint4 mq1 = Ms[wm + g + 8];
        const u32* mw0 = (const u32*)&mq0;
        const u32* mw1 = (const u32*)&mq1;
#pragma unroll
        for (int t = 0; t < 16; t++) {
            int bp = t * 8 + tig * 2;
            u32 b0 = (mw0[bp >> 5] >> (bp & 31)) & 3u;
            u32 b1 = (mw1[bp >> 5] >> (bp & 31)) & 3u;
            sc[t][0] = (b0 & 1u) ? 0.0f : __expf(sc[t][0] * scale) * iv0;
            sc[t][1] = (b0 & 2u) ? 0.0f : __expf(sc[t][1] * scale) * iv0;
            sc[t][2] = (b1 & 1u) ? 0.0f : __expf(sc[t][2] * scale) * iv1;
            sc[t][3] = (b1 & 2u) ? 0.0f : __expf(sc[t][3] * scale) * iv1;
            int col = n0 + t * 8 + tig * 2;
            *(float2*)&ar0[col] = make_float2(sc[t][0], sc[t][1]);
            *(float2*)&ar1[col] = make_float2(sc[t][2], sc[t][3]);
        }

        // repack P (fp32 accum layout) -> fp16 A fragments, k = 128 seq dim
        u32 pa[8][4];
#pragma unroll
        for (int kk = 0; kk < 8; kk++) {
            pa[kk][0] = hpair(sc[2 * kk][0], sc[2 * kk][1]);
            pa[kk][1] = hpair(sc[2 * kk][2], sc[2 * kk][3]);
            pa[kk][2] = hpair(sc[2 * kk + 1][0], sc[2 * kk + 1][1]);
            pa[kk][3] = hpair(sc[2 * kk + 1][2], sc[2 * kk + 1][3]);
        }

        // O += P @ V  (8 k16 steps, d=64 = 4 ldsm4t of n16)
#pragma unroll
        for (int kk = 0; kk < 8; kk++) {
#pragma unroll
            for (int hh = 0; hh < 4; hh++) {
                u32 bv[4];
                ldsm4t(bv, vs_base + (u32)((kk * 16 + bt_k) * PAW + ((hh * 16 + bt_n) >> 1)) * 4u);
                mma16816(o[2 * hh], pa[kk], &bv[0]);
                mma16816(o[2 * hh + 1], pa[kk], &bv[2]);
            }
        }
    }

    int row = m0 + wm + g;
    int row2 = row + 8;
#pragma unroll
    for (int t = 0; t < 8; t++) {
        int col = t * 8 + tig * 2;
        *(u32*)&g_rep16[(size_t)(b * Sq + row) * Dm + h * DP + col] = hpair(o[t][0], o[t][1]);
        *(u32*)&g_rep16[(size_t)(b * Sq + row2) * Dm + h * DP + col] = hpair(o[t][2], o[t][3]);
    }
}

// ---------------------------------------------------------------------------
extern "C" void kernel_launch(void* const* d_in, const int* in_sizes, int n_in,
                              void* d_out, int out_size)
{
    const float* Q    = (const float*)d_in[0];
    const float* K    = (const float*)d_in[1];
    const float* V    = (const float*)d_in[2];
    const float* Mask = (const float*)d_in[3];
    const float* Wq   = (const float*)d_in[4];
    const float* bq   = (const float*)d_in[5];
    const float* Wk   = (const float*)d_in[6];
    const float* bk   = (const float*)d_in[7];
    const float* Wv   = (const float*)d_in[8];
    const float* bv   = (const float*)d_in[9];
    const float* Wo   = (const float*)d_in[10];
    const float* bo   = (const float*)d_in[11];

    float* out = (float*)d_out;

    float* attn;
    const size_t attn_elems = (size_t)NBH * Sq * Sq;
    if ((size_t)out_size >= (size_t)OUT_ELEMS + attn_elems) {
        attn = out + OUT_ELEMS;
    } else {
        void* p = nullptr;
        cudaGetSymbolAddress(&p, g_attn_fallback);
        attn = (float*)p;
    }

    mask_bits_kernel<<<(Bq * Sq * NMW) / 64, 256>>>(Mask);

    dim3 gProj(MTOK / 128, Dm / 128);            // 64 x 8
    proj_mma<<<gProj, 256>>>(Q, Wq, bq, nullptr, 0);
    proj_mma<<<gProj, 256>>>(K, Wk, bk, nullptr, 1);
    proj_mma<<<gProj, 256>>>(V, Wv, bv, nullptr, 2);

    dim3 gAttn(Sq / 128, NBH);                   // 16 x 64
    rowsum_mma<<<gAttn, 256>>>();
    attn_av_mma<<<gAttn, 256>>>(attn);

    proj_mma<<<gProj, 256>>>(nullptr, Wo, bo, out, 3);
}

// round 10
// speedup vs baseline: 1.7546x; 1.5276x over previous
#include <cuda_runtime.h>
#include <cuda_fp16.h>
#include <cstdint>
#include <cstddef>

typedef unsigned int u32;

#define Bq 4
#define Sq 2048
#define Dm 1024
#define Hh 16
#define DP 64
#define MTOK (Bq*Sq)          /* 8192 */
#define NBH  (Bq*Hh)          /* 64   */
#define OUT_ELEMS (MTOK*Dm)   /* 8388608 */
#define NMW (Sq/32)           /* 64 mask words per row */

// Scratch (allocation-free rule: __device__ globals)
__device__ __half g_q16[(size_t)NBH*Sq*DP];
__device__ __half g_k16[(size_t)NBH*Sq*DP];
__device__ __half g_v16[(size_t)NBH*Sq*DP];
__device__ __half g_rep16[(size_t)MTOK*Dm];
__device__ __half g_e16[(size_t)NBH*Sq*Sq];      // unnormalized exp scores
__device__ float  g_inv[(size_t)NBH*Sq];          // 1 / rowsum
__device__ u32    g_mbits[(size_t)Bq*Sq*NMW];
__device__ float  g_attn_fallback[(size_t)NBH*Sq*Sq];

// ---------------------------------------------------------------------------
// helpers
// ---------------------------------------------------------------------------
__device__ __forceinline__ u32 saddr(const void* p) {
    return (u32)__cvta_generic_to_shared(p);
}
__device__ __forceinline__ u32 hpair(float a, float b) {
    __half2 t = __floats2half2_rn(a, b);
    return *reinterpret_cast<u32*>(&t);
}
__device__ __forceinline__ void mma16816(float* c, const u32* a, const u32* b) {
    asm volatile(
        "mma.sync.aligned.m16n8k16.row.col.f32.f16.f16.f32 "
        "{%0,%1,%2,%3},{%4,%5,%6,%7},{%8,%9},{%0,%1,%2,%3};"
        : "+f"(c[0]), "+f"(c[1]), "+f"(c[2]), "+f"(c[3])
        : "r"(a[0]), "r"(a[1]), "r"(a[2]), "r"(a[3]), "r"(b[0]), "r"(b[1]));
}
__device__ __forceinline__ void ldsm4(u32* r, u32 a) {
    asm volatile("ldmatrix.sync.aligned.m8n8.x4.shared.b16 {%0,%1,%2,%3},[%4];"
                 : "=r"(r[0]), "=r"(r[1]), "=r"(r[2]), "=r"(r[3]) : "r"(a));
}
__device__ __forceinline__ void ldsm4t(u32* r, u32 a) {
    asm volatile("ldmatrix.sync.aligned.m8n8.x4.trans.shared.b16 {%0,%1,%2,%3},[%4];"
                 : "=r"(r[0]), "=r"(r[1]), "=r"(r[2]), "=r"(r[3]) : "r"(a));
}
__device__ __forceinline__ void cpa16(u32 dst, const void* src) {
    asm volatile("cp.async.ca.shared.global [%0],[%1],16;\n" :: "r"(dst), "l"(src));
}
__device__ __forceinline__ void cpa_commit() {
    asm volatile("cp.async.commit_group;\n");
}
__device__ __forceinline__ void cpa_wait0() {
    asm volatile("cp.async.wait_group 0;\n");
}

#define PAW 36   /* 64-fp16 row: 32 words + 4 pad (144B pitch) */
#define PBW 68   /* 128-fp16 row: 64 words + 4 pad (272B pitch) */

// ---------------------------------------------------------------------------
// Mask -> bitmask. 1 bit per mask element (1 = masked). Warp ballot pack.
// ---------------------------------------------------------------------------
__global__ __launch_bounds__(256) void mask_bits_kernel(const float* __restrict__ M)
{
    int wgl = blockIdx.x * 8 + (threadIdx.x >> 5);
    int lane = threadIdx.x & 31;
#pragma unroll
    for (int i = 0; i < 8; i++) {
        size_t word = (size_t)wgl * 8 + i;
        float v = M[word * 32 + lane];
        u32 bal = __ballot_sync(0xffffffffu, v != 0.0f);
        if (lane == 0) { g_mbits[word] = bal; }
    }
}

// ---------------------------------------------------------------------------
// Projection GEMM: Y = X @ W + b, M=8192 N=1024 K=1024, fp16 MMA.
// targets 0/1/2: fp32 X -> fp16 head-split out. target 3: g_rep16 -> fp32 out.
// ---------------------------------------------------------------------------
__global__ __launch_bounds__(256) void proj_mma(
    const float* __restrict__ X, const float* __restrict__ W,
    const float* __restrict__ bias, float* __restrict__ dout, int target)
{
    __shared__ __align__(16) u32 As[128 * PAW];
    __shared__ __align__(16) u32 Bs[64 * PBW];

    const int tid = threadIdx.x;
    const int m0 = blockIdx.x * 128, n0 = blockIdx.y * 128;
    const int warp = tid >> 5, lane = tid & 31;
    const int wm = (warp >> 2) * 64, wn = (warp & 3) * 32;
    const int g = lane >> 2, tig = lane & 3;

    const int a_row = (lane & 7) + ((lane >> 3) & 1) * 8;
    const int a_k   = (lane >> 4) * 8;
    const int bt_k  = (lane & 7) + ((lane >> 3) & 1) * 8;
    const int bt_n  = (lane >> 4) * 8;

    const u32 as_base = saddr(As), bs_base = saddr(Bs);

    float acc[4][4][4];
#pragma unroll
    for (int i = 0; i < 4; i++) {
#pragma unroll
        for (int j = 0; j < 4; j++) {
#pragma unroll
            for (int r = 0; r < 4; r++) { acc[i][j][r] = 0.0f; }
        }
    }

    for (int k0 = 0; k0 < Dm; k0 += 64) {
        if (target < 3) {
#pragma unroll
            for (int l = 0; l < 8; l++) {
                int idx = tid + l * 256;
                int r = idx >> 4, q = idx & 15;
                float4 v = *(const float4*)&X[(size_t)(m0 + r) * Dm + k0 + q * 4];
                uint2 w;
                w.x = hpair(v.x, v.y); w.y = hpair(v.z, v.w);
                *(uint2*)&As[r * PAW + q * 2] = w;
            }
        } else {
            const __half* X16 = g_rep16;
#pragma unroll
            for (int l = 0; l < 4; l++) {
                int idx = tid + l * 256;
                int r = idx >> 3, q = idx & 7;
                *(uint4*)&As[r * PAW + q * 4] =
                    *(const uint4*)&X16[(size_t)(m0 + r) * Dm + k0 + q * 8];
            }
        }
#pragma unroll
        for (int l = 0; l < 8; l++) {
            int idx = tid + l * 256;
            int r = idx >> 5, q = idx & 31;
            float4 v = *(const float4*)&W[(size_t)(k0 + r) * Dm + n0 + q * 4];
            uint2 w;
            w.x = hpair(v.x, v.y); w.y = hpair(v.z, v.w);
            *(uint2*)&Bs[r * PBW + q * 2] = w;
        }
        __syncthreads();
#pragma unroll
        for (int ks = 0; ks < 64; ks += 16) {
            u32 af[4][4];
#pragma unroll
            for (int mi = 0; mi < 4; mi++) {
                ldsm4(af[mi], as_base + (u32)((wm + mi * 16 + a_row) * PAW + ((ks + a_k) >> 1)) * 4u);
            }
            u32 bf[2][4];
#pragma unroll
            for (int h = 0; h < 2; h++) {
                ldsm4t(bf[h], bs_base + (u32)((ks + bt_k) * PBW + ((wn + h * 16 + bt_n) >> 1)) * 4u);
            }
#pragma unroll
            for (int mi = 0; mi < 4; mi++) {
#pragma unroll
                for (int j = 0; j < 4; j++) {
                    mma16816(acc[mi][j], af[mi], &bf[j >> 1][(j & 1) * 2]);
                }
            }
        }
        __syncthreads();
    }

    __half* hs_out = (target == 0) ? g_q16 : (target == 1) ? g_k16 : g_v16;
#pragma unroll
    for (int mi = 0; mi < 4; mi++) {
        int row = m0 + wm + mi * 16 + g;
        int row2 = row + 8;
#pragma unroll
        for (int j = 0; j < 4; j++) {
            int col = n0 + wn + j * 8 + tig * 2;
            float b0 = bias[col], b1 = bias[col + 1];
            float c00 = acc[mi][j][0] + b0, c01 = acc[mi][j][1] + b1;
            float c10 = acc[mi][j][2] + b0, c11 = acc[mi][j][3] + b1;
            if (target < 3) {
                int h = col >> 6, dc = col & 63;
                int bi = row >> 11, sl = row & 2047;
                int bi2 = row2 >> 11, sl2 = row2 & 2047;
                *(u32*)&hs_out[((size_t)(bi * Hh + h) * Sq + sl) * DP + dc] = hpair(c00, c01);
                *(u32*)&hs_out[((size_t)(bi2 * Hh + h) * Sq + sl2) * DP + dc] = hpair(c10, c11);
            } else {
                *(float2*)&dout[(size_t)row * Dm + col] = make_float2(c00, c01);
                *(float2*)&dout[(size_t)row2 * Dm + col] = make_float2(c10, c11);
            }
        }
    }
}

// ---------------------------------------------------------------------------
// Fused flash attention pass: one block owns 128 q-rows of one (b,h).
// Per K/V tile: QK mma -> exp -> store e16 -> rowsum regs -> P repack -> O+=PV.
// cp.async double-buffered K/V/mask tiles. 94KB dynamic smem.
// End: g_inv = 1/rowsum; g_rep16 = O * inv.
// ---------------------------------------------------------------------------
#define SM_QS   0
#define SM_KS   18432
#define SM_VS   55296
#define SM_MS   92160
#define SM_TOT  96256

__global__ __launch_bounds__(256) void flash_mma()
{
    extern __shared__ __align__(16) char sm[];
    const int tid = threadIdx.x;
    const int bh = blockIdx.y, b = bh >> 4, h = bh & 15;
    const int m0 = blockIdx.x * 128;
    const __half* Qp = g_q16 + (size_t)bh * Sq * DP;
    const __half* Kp = g_k16 + (size_t)bh * Sq * DP;
    const __half* Vp = g_v16 + (size_t)bh * Sq * DP;
    const int warp = tid >> 5, lane = tid & 31;
    const int wm = warp * 16;
    const int g = lane >> 2, tig = lane & 3;

    const int a_row = (lane & 7) + ((lane >> 3) & 1) * 8;
    const int a_k   = (lane >> 4) * 8;
    const int bn_n  = (lane & 7) + (lane >> 4) * 8;
    const int bn_k  = ((lane >> 3) & 1) * 8;
    const int bt_k  = (lane & 7) + ((lane >> 3) & 1) * 8;
    const int bt_n  = (lane >> 4) * 8;

    const u32 smb = saddr(sm);
    u32* Qs = (u32*)(sm + SM_QS);

    // load Q tile (plain)
#pragma unroll
    for (int l = 0; l < 4; l++) {
        int idx = tid + l * 256;
        int r = idx >> 3, q = idx & 7;
        *(uint4*)&Qs[r * PAW + q * 4] = *(const uint4*)&Qp[(size_t)(m0 + r) * DP + q * 8];
    }

    // prefetch tile 0 into buffer 0
    {
        u32 ksb = smb + SM_KS, vsb = smb + SM_VS, msb = smb + SM_MS;
#pragma unroll
        for (int l = 0; l < 4; l++) {
            int idx = tid + l * 256;
            int r = idx >> 3, c = idx & 7;
            cpa16(ksb + (u32)(r * PAW + c * 4) * 4u, Kp + (size_t)r * DP + c * 8);
            cpa16(vsb + (u32)(r * PAW + c * 4) * 4u, Vp + (size_t)r * DP + c * 8);
        }
        if (tid < 128) {
            cpa16(msb + tid * 16, g_mbits + (size_t)(b * Sq + m0 + tid) * NMW);
        }
        cpa_commit();
    }
    __syncthreads();   // Qs visible

    u32 af[4][4];
#pragma unroll
    for (int ks = 0; ks < 4; ks++) {
        ldsm4(af[ks], smb + SM_QS + (u32)((wm + a_row) * PAW + ((ks * 16 + a_k) >> 1)) * 4u);
    }

    float o[8][4];
#pragma unroll
    for (int t = 0; t < 8; t++) {
#pragma unroll
        for (int r = 0; r < 4; r++) { o[t][r] = 0.0f; }
    }
    float rs0 = 0.0f, rs1 = 0.0f;

    const float scale = 0.125f;
    __half* er0 = g_e16 + ((size_t)bh * Sq + m0 + wm + g) * Sq;
    __half* er1 = g_e16 + ((size_t)bh * Sq + m0 + wm + g + 8) * Sq;

    int buf = 0;
    for (int it = 0; it < 16; it++) {
        int n0 = it * 128;
        cpa_wait0();
        __syncthreads();

        if (it < 15) {
            int nn = n0 + 128;
            int nb = buf ^ 1;
            u32 ksb = smb + SM_KS + nb * 18432;
            u32 vsb = smb + SM_VS + nb * 18432;
            u32 msb = smb + SM_MS + nb * 2048;
#pragma unroll
            for (int l = 0; l < 4; l++) {
                int idx = tid + l * 256;
                int r = idx >> 3, c = idx & 7;
                cpa16(ksb + (u32)(r * PAW + c * 4) * 4u, Kp + (size_t)(nn + r) * DP + c * 8);
                cpa16(vsb + (u32)(r * PAW + c * 4) * 4u, Vp + (size_t)(nn + r) * DP + c * 8);
            }
            if (tid < 128) {
                cpa16(msb + tid * 16, g_mbits + (size_t)(b * Sq + m0 + tid) * NMW + (nn >> 5));
            }
            cpa_commit();
        }

        const u32 ks_base = smb + SM_KS + buf * 18432;
        const u32 vs_base = smb + SM_VS + buf * 18432;
        const uint4* Ms = (const uint4*)(sm + SM_MS + buf * 2048);

        float sc[16][4];
#pragma unroll
        for (int t = 0; t < 16; t++) {
#pragma unroll
            for (int r = 0; r < 4; r++) { sc[t][r] = 0.0f; }
        }
#pragma unroll
        for (int ks = 0; ks < 4; ks++) {
#pragma unroll
            for (int h6 = 0; h6 < 8; h6++) {
                u32 bq[4];
                ldsm4(bq, ks_base + (u32)((h6 * 16 + bn_n) * PAW + ((ks * 16 + bn_k) >> 1)) * 4u);
                mma16816(sc[2 * h6], af[ks], &bq[0]);
                mma16816(sc[2 * h6 + 1], af[ks], &bq[2]);
            }
        }

        uint4 mq0 = Ms[wm + g];
        uint4 mq1 = Ms[wm + g + 8];
        const u32* mw0 = (const u32*)&mq0;
        const u32* mw1 = (const u32*)&mq1;
        u32 pa[8][4];
#pragma unroll
        for (int t = 0; t < 16; t++) {
            int bp = t * 8 + tig * 2;
            u32 b0 = (mw0[bp >> 5] >> (bp & 31)) & 3u;
            u32 b1 = (mw1[bp >> 5] >> (bp & 31)) & 3u;
            float e0 = (b0 & 1u) ? 0.0f : __expf(sc[t][0] * scale);
            float e1 = (b0 & 2u) ? 0.0f : __expf(sc[t][1] * scale);
            float e2 = (b1 & 1u) ? 0.0f : __expf(sc[t][2] * scale);
            float e3 = (b1 & 2u) ? 0.0f : __expf(sc[t][3] * scale);
            rs0 += e0 + e1;
            rs1 += e2 + e3;
            int col = n0 + t * 8 + tig * 2;
            u32 w01 = hpair(e0, e1);
            u32 w23 = hpair(e2, e3);
            *(u32*)&er0[col] = w01;
            *(u32*)&er1[col] = w23;
            pa[t >> 1][(t & 1) * 2]     = w01;
            pa[t >> 1][(t & 1) * 2 + 1] = w23;
        }

        // O += P @ V
#pragma unroll
        for (int kk = 0; kk < 8; kk++) {
#pragma unroll
            for (int hh = 0; hh < 4; hh++) {
                u32 bv[4];
                ldsm4t(bv, vs_base + (u32)((kk * 16 + bt_k) * PAW + ((hh * 16 + bt_n) >> 1)) * 4u);
                mma16816(o[2 * hh], pa[kk], &bv[0]);
                mma16816(o[2 * hh + 1], pa[kk], &bv[2]);
            }
        }
        buf ^= 1;
    }

    rs0 += __shfl_xor_sync(0xffffffffu, rs0, 1);
    rs0 += __shfl_xor_sync(0xffffffffu, rs0, 2);
    rs1 += __shfl_xor_sync(0xffffffffu, rs1, 1);
    rs1 += __shfl_xor_sync(0xffffffffu, rs1, 2);
    float iv0 = 1.0f / rs0;
    float iv1 = 1.0f / rs1;
    if (tig == 0) {
        g_inv[(size_t)bh * Sq + m0 + wm + g] = iv0;
        g_inv[(size_t)bh * Sq + m0 + wm + g + 8] = iv1;
    }

    int row = m0 + wm + g;
    int row2 = row + 8;
#pragma unroll
    for (int t = 0; t < 8; t++) {
        int col = t * 8 + tig * 2;
        *(u32*)&g_rep16[(size_t)(b * Sq + row) * Dm + h * DP + col] =
            hpair(o[t][0] * iv0, o[t][1] * iv0);
        *(u32*)&g_rep16[(size_t)(b * Sq + row2) * Dm + h * DP + col] =
            hpair(o[t][2] * iv1, o[t][3] * iv1);
    }
}

// ---------------------------------------------------------------------------
// Normalize: attn[row][col] = e16[row][col] * inv[row]. Pure streaming.
// One block per row; thread t handles 8 halves.
// ---------------------------------------------------------------------------
__global__ __launch_bounds__(256) void norm_e_kernel(float* __restrict__ attn)
{
    size_t row = blockIdx.x;
    const __half* er = g_e16 + row * Sq;
    float* ar = attn + row * Sq;
    float iv = g_inv[row];
    int t = threadIdx.x;
    uint4 w = *(const uint4*)&er[t * 8];
    const __half2* hp = (const __half2*)&w;
    float2 p0 = __half22float2(hp[0]);
    float2 p1 = __half22float2(hp[1]);
    float2 p2 = __half22float2(hp[2]);
    float2 p3 = __half22float2(hp[3]);
    float4 o0 = make_float4(p0.x * iv, p0.y * iv, p1.x * iv, p1.y * iv);
    float4 o1 = make_float4(p2.x * iv, p2.y * iv, p3.x * iv, p3.y * iv);
    *(float4*)&ar[t * 8] = o0;
    *(float4*)&ar[t * 8 + 4] = o1;
}

// ---------------------------------------------------------------------------
extern "C" void kernel_launch(void* const* d_in, const int* in_sizes, int n_in,
                              void* d_out, int out_size)
{
    const float* Q    = (const float*)d_in[0];
    const float* K    = (const float*)d_in[1];
    const float* V    = (const float*)d_in[2];
    const float* Mask = (const float*)d_in[3];
    const float* Wq   = (const float*)d_in[4];
    const float* bq   = (const float*)d_in[5];
    const float* Wk   = (const float*)d_in[6];
    const float* bk   = (const float*)d_in[7];
    const float* Wv   = (const float*)d_in[8];
    const float* bv   = (const float*)d_in[9];
    const float* Wo   = (const float*)d_in[10];
    const float* bo   = (const float*)d_in[11];

    float* out = (float*)d_out;

    float* attn;
    const size_t attn_elems = (size_t)NBH * Sq * Sq;
    if ((size_t)out_size >= (size_t)OUT_ELEMS + attn_elems) {
        attn = out + OUT_ELEMS;
    } else {
        void* p = nullptr;
        cudaGetSymbolAddress(&p, g_attn_fallback);
        attn = (float*)p;
    }

    static bool smem_set = false;
    if (!smem_set) {
        cudaFuncSetAttribute(flash_mma, cudaFuncAttributeMaxDynamicSharedMemorySize, SM_TOT);
        smem_set = true;
    }

    mask_bits_kernel<<<(Bq * Sq * NMW) / 64, 256>>>(Mask);

    dim3 gProj(MTOK / 128, Dm / 128);            // 64 x 8
    proj_mma<<<gProj, 256>>>(Q, Wq, bq, nullptr, 0);
    proj_mma<<<gProj, 256>>>(K, Wk, bk, nullptr, 1);
    proj_mma<<<gProj, 256>>>(V, Wv, bv, nullptr, 2);

    dim3 gAttn(Sq / 128, NBH);                   // 16 x 64
    flash_mma<<<gAttn, 256, SM_TOT>>>();

    norm_e_kernel<<<NBH * Sq, 256>>>(attn);      // 131072 blocks

    proj_mma<<<gProj, 256>>>(nullptr, Wo, bo, out, 3);
}

// round 11
// speedup vs baseline: 1.9139x; 1.0908x over previous
#include <cuda_runtime.h>
#include <cuda_fp16.h>
#include <cstdint>
#include <cstddef>

typedef unsigned int u32;

#define Bq 4
#define Sq 2048
#define Dm 1024
#define Hh 16
#define DP 64
#define MTOK (Bq*Sq)          /* 8192 */
#define NBH  (Bq*Hh)          /* 64   */
#define OUT_ELEMS (MTOK*Dm)   /* 8388608 */
#define NMW (Sq/32)           /* 64 mask words per row */

// Scratch (allocation-free rule: __device__ globals)
__device__ __half g_q16[(size_t)NBH*Sq*DP];
__device__ __half g_k16[(size_t)NBH*Sq*DP];
__device__ __half g_v16[(size_t)NBH*Sq*DP];
__device__ __half g_rep16[(size_t)MTOK*Dm];
__device__ __half g_e16[(size_t)NBH*Sq*Sq];      // unnormalized exp scores
__device__ float  g_inv[(size_t)NBH*Sq];          // 1 / rowsum
__device__ u32    g_mbits[(size_t)Bq*Sq*NMW];
__device__ float  g_attn_fallback[(size_t)NBH*Sq*Sq];

// fp16 copies of inputs & weights (one-time convert)
__device__ __half g_xq[(size_t)MTOK*Dm];
__device__ __half g_xk[(size_t)MTOK*Dm];
__device__ __half g_xv[(size_t)MTOK*Dm];
__device__ __half g_wq[(size_t)Dm*Dm];
__device__ __half g_wk[(size_t)Dm*Dm];
__device__ __half g_wv[(size_t)Dm*Dm];
__device__ __half g_wo[(size_t)Dm*Dm];

// ---------------------------------------------------------------------------
// helpers
// ---------------------------------------------------------------------------
__device__ __forceinline__ u32 saddr(const void* p) {
    return (u32)__cvta_generic_to_shared(p);
}
__device__ __forceinline__ u32 hpair(float a, float b) {
    __half2 t = __floats2half2_rn(a, b);
    return *reinterpret_cast<u32*>(&t);
}
__device__ __forceinline__ void mma16816(float* c, const u32* a, const u32* b) {
    asm volatile(
        "mma.sync.aligned.m16n8k16.row.col.f32.f16.f16.f32 "
        "{%0,%1,%2,%3},{%4,%5,%6,%7},{%8,%9},{%0,%1,%2,%3};"
        : "+f"(c[0]), "+f"(c[1]), "+f"(c[2]), "+f"(c[3])
        : "r"(a[0]), "r"(a[1]), "r"(a[2]), "r"(a[3]), "r"(b[0]), "r"(b[1]));
}
__device__ __forceinline__ void ldsm4(u32* r, u32 a) {
    asm volatile("ldmatrix.sync.aligned.m8n8.x4.shared.b16 {%0,%1,%2,%3},[%4];"
                 : "=r"(r[0]), "=r"(r[1]), "=r"(r[2]), "=r"(r[3]) : "r"(a));
}
__device__ __forceinline__ void ldsm4t(u32* r, u32 a) {
    asm volatile("ldmatrix.sync.aligned.m8n8.x4.trans.shared.b16 {%0,%1,%2,%3},[%4];"
                 : "=r"(r[0]), "=r"(r[1]), "=r"(r[2]), "=r"(r[3]) : "r"(a));
}
__device__ __forceinline__ void cpa16(u32 dst, const void* src) {
    asm volatile("cp.async.ca.shared.global [%0],[%1],16;\n" :: "r"(dst), "l"(src));
}
__device__ __forceinline__ void cpa_commit() {
    asm volatile("cp.async.commit_group;\n");
}
__device__ __forceinline__ void cpa_wait0() {
    asm volatile("cp.async.wait_group 0;\n");
}

#define PAW 36   /* 64-fp16 row: 32 words + 4 pad (144B pitch) */
#define PBW 68   /* 128-fp16 row: 64 words + 4 pad (272B pitch) */

// ---------------------------------------------------------------------------
// fp32 -> fp16 streaming convert (8 elements / thread / iter)
// ---------------------------------------------------------------------------
__global__ __launch_bounds__(256) void cvt16_kernel(
    const float* __restrict__ in, __half* __restrict__ out, int n8)
{
    int i = blockIdx.x * 256 + threadIdx.x;
    int stride = gridDim.x * 256;
    for (; i < n8; i += stride) {
        float4 a = *(const float4*)&in[(size_t)i * 8];
        float4 b = *(const float4*)&in[(size_t)i * 8 + 4];
        uint4 w;
        w.x = hpair(a.x, a.y); w.y = hpair(a.z, a.w);
        w.z = hpair(b.x, b.y); w.w = hpair(b.z, b.w);
        *(uint4*)&out[(size_t)i * 8] = w;
    }
}

// ---------------------------------------------------------------------------
// Mask -> bitmask. 1 bit per mask element (1 = masked). Warp ballot pack.
// ---------------------------------------------------------------------------
__global__ __launch_bounds__(256) void mask_bits_kernel(const float* __restrict__ M)
{
    int wgl = blockIdx.x * 8 + (threadIdx.x >> 5);
    int lane = threadIdx.x & 31;
#pragma unroll
    for (int i = 0; i < 8; i++) {
        size_t word = (size_t)wgl * 8 + i;
        float v = M[word * 32 + lane];
        u32 bal = __ballot_sync(0xffffffffu, v != 0.0f);
        if (lane == 0) { g_mbits[word] = bal; }
    }
}

// ---------------------------------------------------------------------------
// Projection GEMM, pure fp16 + cp.async double buffer.
// Y = X16 @ W16 + b, M=8192 N=1024 K=1024.
// targets 0/1/2 -> fp16 head-split out; 3 -> fp32 row-major dout.
// dyn smem: X 2x18432 + W 2x17408 = 71680 B.
// ---------------------------------------------------------------------------
#define PJ_XS0 0
#define PJ_XS1 18432
#define PJ_WS0 36864
#define PJ_WS1 54272
#define PJ_TOT 71680

__global__ __launch_bounds__(256) void proj_mma(
    const __half* __restrict__ X16, const __half* __restrict__ W16,
    const float* __restrict__ bias, float* __restrict__ dout, int target)
{
    extern __shared__ __align__(16) char sm[];

    const int tid = threadIdx.x;
    const int m0 = blockIdx.x * 128, n0 = blockIdx.y * 128;
    const int warp = tid >> 5, lane = tid & 31;
    const int wm = (warp >> 2) * 64, wn = (warp & 3) * 32;
    const int g = lane >> 2, tig = lane & 3;

    const int a_row = (lane & 7) + ((lane >> 3) & 1) * 8;
    const int a_k   = (lane >> 4) * 8;
    const int bt_k  = (lane & 7) + ((lane >> 3) & 1) * 8;
    const int bt_n  = (lane >> 4) * 8;

    const u32 smb = saddr(sm);

    float acc[4][4][4];
#pragma unroll
    for (int i = 0; i < 4; i++) {
#pragma unroll
        for (int j = 0; j < 4; j++) {
#pragma unroll
            for (int r = 0; r < 4; r++) { acc[i][j][r] = 0.0f; }
        }
    }

    // prefetch k-tile 0 into buffer 0
    {
        u32 xd = smb + PJ_XS0, wd = smb + PJ_WS0;
#pragma unroll
        for (int l = 0; l < 4; l++) {
            int idx = tid + l * 256;
            int r = idx >> 3, c = idx & 7;                 // X: 128 rows x 8 chunks
            cpa16(xd + (u32)(r * PAW + c * 4) * 4u, X16 + (size_t)(m0 + r) * Dm + c * 8);
        }
#pragma unroll
        for (int l = 0; l < 4; l++) {
            int idx = tid + l * 256;
            int r = idx >> 4, c = idx & 15;                // W: 64 rows x 16 chunks
            cpa16(wd + (u32)(r * PBW + c * 4) * 4u, W16 + (size_t)r * Dm + n0 + c * 8);
        }
        cpa_commit();
    }

    int buf = 0;
    for (int it = 0; it < 16; it++) {
        cpa_wait0();
        __syncthreads();

        if (it < 15) {
            int kk0 = (it + 1) * 64;
            int nb = buf ^ 1;
            u32 xd = smb + (nb ? PJ_XS1 : PJ_XS0);
            u32 wd = smb + (nb ? PJ_WS1 : PJ_WS0);
#pragma unroll
            for (int l = 0; l < 4; l++) {
                int idx = tid + l * 256;
                int r = idx >> 3, c = idx & 7;
                cpa16(xd + (u32)(r * PAW + c * 4) * 4u, X16 + (size_t)(m0 + r) * Dm + kk0 + c * 8);
            }
#pragma unroll
            for (int l = 0; l < 4; l++) {
                int idx = tid + l * 256;
                int r = idx >> 4, c = idx & 15;
                cpa16(wd + (u32)(r * PBW + c * 4) * 4u, W16 + (size_t)(kk0 + r) * Dm + n0 + c * 8);
            }
            cpa_commit();
        }

        const u32 as_base = smb + (buf ? PJ_XS1 : PJ_XS0);
        const u32 bs_base = smb + (buf ? PJ_WS1 : PJ_WS0);

#pragma unroll
        for (int ks = 0; ks < 64; ks += 16) {
            u32 af[4][4];
#pragma unroll
            for (int mi = 0; mi < 4; mi++) {
                ldsm4(af[mi], as_base + (u32)((wm + mi * 16 + a_row) * PAW + ((ks + a_k) >> 1)) * 4u);
            }
            u32 bf[2][4];
#pragma unroll
            for (int h = 0; h < 2; h++) {
                ldsm4t(bf[h], bs_base + (u32)((ks + bt_k) * PBW + ((wn + h * 16 + bt_n) >> 1)) * 4u);
            }
#pragma unroll
            for (int mi = 0; mi < 4; mi++) {
#pragma unroll
                for (int j = 0; j < 4; j++) {
                    mma16816(acc[mi][j], af[mi], &bf[j >> 1][(j & 1) * 2]);
                }
            }
        }
        __syncthreads();
        buf ^= 1;
    }

    __half* hs_out = (target == 0) ? g_q16 : (target == 1) ? g_k16 : g_v16;
#pragma unroll
    for (int mi = 0; mi < 4; mi++) {
        int row = m0 + wm + mi * 16 + g;
        int row2 = row + 8;
#pragma unroll
        for (int j = 0; j < 4; j++) {
            int col = n0 + wn + j * 8 + tig * 2;
            float b0 = bias[col], b1 = bias[col + 1];
            float c00 = acc[mi][j][0] + b0, c01 = acc[mi][j][1] + b1;
            float c10 = acc[mi][j][2] + b0, c11 = acc[mi][j][3] + b1;
            if (target < 3) {
                int h = col >> 6, dc = col & 63;
                int bi = row >> 11, sl = row & 2047;
                int bi2 = row2 >> 11, sl2 = row2 & 2047;
                *(u32*)&hs_out[((size_t)(bi * Hh + h) * Sq + sl) * DP + dc] = hpair(c00, c01);
                *(u32*)&hs_out[((size_t)(bi2 * Hh + h) * Sq + sl2) * DP + dc] = hpair(c10, c11);
            } else {
                *(float2*)&dout[(size_t)row * Dm + col] = make_float2(c00, c01);
                *(float2*)&dout[(size_t)row2 * Dm + col] = make_float2(c10, c11);
            }
        }
    }
}

// ---------------------------------------------------------------------------
// Fused flash attention pass (unchanged from R10).
// ---------------------------------------------------------------------------
#define SM_QS   0
#define SM_KS   18432
#define SM_VS   55296
#define SM_MS   92160
#define SM_TOT  96256

__global__ __launch_bounds__(256) void flash_mma()
{
    extern __shared__ __align__(16) char sm[];
    const int tid = threadIdx.x;
    const int bh = blockIdx.y, b = bh >> 4, h = bh & 15;
    const int m0 = blockIdx.x * 128;
    const __half* Qp = g_q16 + (size_t)bh * Sq * DP;
    const __half* Kp = g_k16 + (size_t)bh * Sq * DP;
    const __half* Vp = g_v16 + (size_t)bh * Sq * DP;
    const int warp = tid >> 5, lane = tid & 31;
    const int wm = warp * 16;
    const int g = lane >> 2, tig = lane & 3;

    const int a_row = (lane & 7) + ((lane >> 3) & 1) * 8;
    const int a_k   = (lane >> 4) * 8;
    const int bn_n  = (lane & 7) + (lane >> 4) * 8;
    const int bn_k  = ((lane >> 3) & 1) * 8;
    const int bt_k  = (lane & 7) + ((lane >> 3) & 1) * 8;
    const int bt_n  = (lane >> 4) * 8;

    const u32 smb = saddr(sm);
    u32* Qs = (u32*)(sm + SM_QS);

#pragma unroll
    for (int l = 0; l < 4; l++) {
        int idx = tid + l * 256;
        int r = idx >> 3, q = idx & 7;
        *(uint4*)&Qs[r * PAW + q * 4] = *(const uint4*)&Qp[(size_t)(m0 + r) * DP + q * 8];
    }

    {
        u32 ksb = smb + SM_KS, vsb = smb + SM_VS, msb = smb + SM_MS;
#pragma unroll
        for (int l = 0; l < 4; l++) {
            int idx = tid + l * 256;
            int r = idx >> 3, c = idx & 7;
            cpa16(ksb + (u32)(r * PAW + c * 4) * 4u, Kp + (size_t)r * DP + c * 8);
            cpa16(vsb + (u32)(r * PAW + c * 4) * 4u, Vp + (size_t)r * DP + c * 8);
        }
        if (tid < 128) {
            cpa16(msb + tid * 16, g_mbits + (size_t)(b * Sq + m0 + tid) * NMW);
        }
        cpa_commit();
    }
    __syncthreads();

    u32 af[4][4];
#pragma unroll
    for (int ks = 0; ks < 4; ks++) {
        ldsm4(af[ks], smb + SM_QS + (u32)((wm + a_row) * PAW + ((ks * 16 + a_k) >> 1)) * 4u);
    }

    float o[8][4];
#pragma unroll
    for (int t = 0; t < 8; t++) {
#pragma unroll
        for (int r = 0; r < 4; r++) { o[t][r] = 0.0f; }
    }
    float rs0 = 0.0f, rs1 = 0.0f;

    const float scale = 0.125f;
    __half* er0 = g_e16 + ((size_t)bh * Sq + m0 + wm + g) * Sq;
    __half* er1 = g_e16 + ((size_t)bh * Sq + m0 + wm + g + 8) * Sq;

    int buf = 0;
    for (int it = 0; it < 16; it++) {
        int n0 = it * 128;
        cpa_wait0();
        __syncthreads();

        if (it < 15) {
            int nn = n0 + 128;
            int nb = buf ^ 1;
            u32 ksb = smb + SM_KS + nb * 18432;
            u32 vsb = smb + SM_VS + nb * 18432;
            u32 msb = smb + SM_MS + nb * 2048;
#pragma unroll
            for (int l = 0; l < 4; l++) {
                int idx = tid + l * 256;
                int r = idx >> 3, c = idx & 7;
                cpa16(ksb + (u32)(r * PAW + c * 4) * 4u, Kp + (size_t)(nn + r) * DP + c * 8);
                cpa16(vsb + (u32)(r * PAW + c * 4) * 4u, Vp + (size_t)(nn + r) * DP + c * 8);
            }
            if (tid < 128) {
                cpa16(msb + tid * 16, g_mbits + (size_t)(b * Sq + m0 + tid) * NMW + (nn >> 5));
            }
            cpa_commit();
        }

        const u32 ks_base = smb + SM_KS + buf * 18432;
        const u32 vs_base = smb + SM_VS + buf * 18432;
        const uint4* Ms = (const uint4*)(sm + SM_MS + buf * 2048);

        float sc[16][4];
#pragma unroll
        for (int t = 0; t < 16; t++) {
#pragma unroll
            for (int r = 0; r < 4; r++) { sc[t][r] = 0.0f; }
        }
#pragma unroll
        for (int ks = 0; ks < 4; ks++) {
#pragma unroll
            for (int h6 = 0; h6 < 8; h6++) {
                u32 bq[4];
                ldsm4(bq, ks_base + (u32)((h6 * 16 + bn_n) * PAW + ((ks * 16 + bn_k) >> 1)) * 4u);
                mma16816(sc[2 * h6], af[ks], &bq[0]);
                mma16816(sc[2 * h6 + 1], af[ks], &bq[2]);
            }
        }

        uint4 mq0 = Ms[wm + g];
        uint4 mq1 = Ms[wm + g + 8];
        const u32* mw0 = (const u32*)&mq0;
        const u32* mw1 = (const u32*)&mq1;
        u32 pa[8][4];
#pragma unroll
        for (int t = 0; t < 16; t++) {
            int bp = t * 8 + tig * 2;
            u32 b0 = (mw0[bp >> 5] >> (bp & 31)) & 3u;
            u32 b1 = (mw1[bp >> 5] >> (bp & 31)) & 3u;
            float e0 = (b0 & 1u) ? 0.0f : __expf(sc[t][0] * scale);
            float e1 = (b0 & 2u) ? 0.0f : __expf(sc[t][1] * scale);
            float e2 = (b1 & 1u) ? 0.0f : __expf(sc[t][2] * scale);
            float e3 = (b1 & 2u) ? 0.0f : __expf(sc[t][3] * scale);
            rs0 += e0 + e1;
            rs1 += e2 + e3;
            int col = n0 + t * 8 + tig * 2;
            u32 w01 = hpair(e0, e1);
            u32 w23 = hpair(e2, e3);
            *(u32*)&er0[col] = w01;
            *(u32*)&er1[col] = w23;
            pa[t >> 1][(t & 1) * 2]     = w01;
            pa[t >> 1][(t & 1) * 2 + 1] = w23;
        }

#pragma unroll
        for (int kk = 0; kk < 8; kk++) {
#pragma unroll
            for (int hh = 0; hh < 4; hh++) {
                u32 bv[4];
                ldsm4t(bv, vs_base + (u32)((kk * 16 + bt_k) * PAW + ((hh * 16 + bt_n) >> 1)) * 4u);
                mma16816(o[2 * hh], pa[kk], &bv[0]);
                mma16816(o[2 * hh + 1], pa[kk], &bv[2]);
            }
        }
        buf ^= 1;
    }

    rs0 += __shfl_xor_sync(0xffffffffu, rs0, 1);
    rs0 += __shfl_xor_sync(0xffffffffu, rs0, 2);
    rs1 += __shfl_xor_sync(0xffffffffu, rs1, 1);
    rs1 += __shfl_xor_sync(0xffffffffu, rs1, 2);
    float iv0 = 1.0f / rs0;
    float iv1 = 1.0f / rs1;
    if (tig == 0) {
        g_inv[(size_t)bh * Sq + m0 + wm + g] = iv0;
        g_inv[(size_t)bh * Sq + m0 + wm + g + 8] = iv1;
    }

    int row = m0 + wm + g;
    int row2 = row + 8;
#pragma unroll
    for (int t = 0; t < 8; t++) {
        int col = t * 8 + tig * 2;
        *(u32*)&g_rep16[(size_t)(b * Sq + row) * Dm + h * DP + col] =
            hpair(o[t][0] * iv0, o[t][1] * iv0);
        *(u32*)&g_rep16[(size_t)(b * Sq + row2) * Dm + h * DP + col] =
            hpair(o[t][2] * iv1, o[t][3] * iv1);
    }
}

// ---------------------------------------------------------------------------
// Normalize: attn[row][col] = e16[row][col] * inv[row]. Pure streaming.
// ---------------------------------------------------------------------------
__global__ __launch_bounds__(256) void norm_e_kernel(float* __restrict__ attn)
{
    size_t row = blockIdx.x;
    const __half* er = g_e16 + row * Sq;
    float* ar = attn + row * Sq;
    float iv = g_inv[row];
    int t = threadIdx.x;
    uint4 w = *(const uint4*)&er[t * 8];
    const __half2* hp = (const __half2*)&w;
    float2 p0 = __half22float2(hp[0]);
    float2 p1 = __half22float2(hp[1]);
    float2 p2 = __half22float2(hp[2]);
    float2 p3 = __half22float2(hp[3]);
    float4 o0 = make_float4(p0.x * iv, p0.y * iv, p1.x * iv, p1.y * iv);
    float4 o1 = make_float4(p2.x * iv, p2.y * iv, p3.x * iv, p3.y * iv);
    *(float4*)&ar[t * 8] = o0;
    *(float4*)&ar[t * 8 + 4] = o1;
}

// ---------------------------------------------------------------------------
extern "C" void kernel_launch(void* const* d_in, const int* in_sizes, int n_in,
                              void* d_out, int out_size)
{
    const float* Q    = (const float*)d_in[0];
    const float* K    = (const float*)d_in[1];
    const float* V    = (const float*)d_in[2];
    const float* Mask = (const float*)d_in[3];
    const float* Wq   = (const float*)d_in[4];
    const float* bq   = (const float*)d_in[5];
    const float* Wk   = (const float*)d_in[6];
    const float* bk   = (const float*)d_in[7];
    const float* Wv   = (const float*)d_in[8];
    const float* bv   = (const float*)d_in[9];
    const float* Wo   = (const float*)d_in[10];
    const float* bo   = (const float*)d_in[11];

    float* out = (float*)d_out;

    float* attn;
    const size_t attn_elems = (size_t)NBH * Sq * Sq;
    if ((size_t)out_size >= (size_t)OUT_ELEMS + attn_elems) {
        attn = out + OUT_ELEMS;
    } else {
        void* p = nullptr;
        cudaGetSymbolAddress(&p, g_attn_fallback);
        attn = (float*)p;
    }

    static __half *xq, *xk, *xv, *wq, *wk, *wv, *wo;
    static bool init_done = false;
    if (!init_done) {
        cudaFuncSetAttribute(flash_mma, cudaFuncAttributeMaxDynamicSharedMemorySize, SM_TOT);
        cudaFuncSetAttribute(proj_mma, cudaFuncAttributeMaxDynamicSharedMemorySize, PJ_TOT);
        void* p;
        cudaGetSymbolAddress(&p, g_xq); xq = (__half*)p;
        cudaGetSymbolAddress(&p, g_xk); xk = (__half*)p;
        cudaGetSymbolAddress(&p, g_xv); xv = (__half*)p;
        cudaGetSymbolAddress(&p, g_wq); wq = (__half*)p;
        cudaGetSymbolAddress(&p, g_wk); wk = (__half*)p;
        cudaGetSymbolAddress(&p, g_wv); wv = (__half*)p;
        cudaGetSymbolAddress(&p, g_wo); wo = (__half*)p;
        init_done = true;
    }

    // one-time-per-call converts (cheap, streaming)
    cvt16_kernel<<<2048, 256>>>(Q, xq, OUT_ELEMS / 8);
    cvt16_kernel<<<2048, 256>>>(K, xk, OUT_ELEMS / 8);
    cvt16_kernel<<<2048, 256>>>(V, xv, OUT_ELEMS / 8);
    cvt16_kernel<<<512, 256>>>(Wq, wq, (Dm * Dm) / 8);
    cvt16_kernel<<<512, 256>>>(Wk, wk, (Dm * Dm) / 8);
    cvt16_kernel<<<512, 256>>>(Wv, wv, (Dm * Dm) / 8);
    cvt16_kernel<<<512, 256>>>(Wo, wo, (Dm * Dm) / 8);

    mask_bits_kernel<<<(Bq * Sq * NMW) / 64, 256>>>(Mask);

    dim3 gProj(MTOK / 128, Dm / 128);            // 64 x 8
    proj_mma<<<gProj, 256, PJ_TOT>>>(xq, wq, bq, nullptr, 0);
    proj_mma<<<gProj, 256, PJ_TOT>>>(xk, wk, bk, nullptr, 1);
    proj_mma<<<gProj, 256, PJ_TOT>>>(xv, wv, bv, nullptr, 2);

    dim3 gAttn(Sq / 128, NBH);                   // 16 x 64
    flash_mma<<<gAttn, 256, SM_TOT>>>();

    norm_e_kernel<<<NBH * Sq, 256>>>(attn);      // 131072 blocks

    __half* rep;
    { void* p; cudaGetSymbolAddress(&p, g_rep16); rep = (__half*)p; }
    proj_mma<<<gProj, 256, PJ_TOT>>>(rep, wo, bo, out, 3);
}